// round 4
// baseline (speedup 1.0000x reference)
#include <cuda_runtime.h>
#include <cstdint>
#include <cstddef>

// Problem dims
#define T_DIM 1024
#define H_DIM 512
#define B_DIM 64
#define NM    18          // 18 recurrent matrices: i,f,c,o + 7 aux-i + 7 aux-c
#define NBLK  144         // persistent grid (<= 148 SMs, co-resident)
#define THR   128

// ---------------------------------------------------------------------------
// Device-global scratch (allocation-free rule: __device__ arrays). ~20MB total.
// ---------------------------------------------------------------------------
// Ut[m][g][h] = U_m[h][g] for m<18 ; m==18 holds W_a transposed (Wt[g][h])
__device__ float g_Ut[19 * H_DIM * H_DIM];
__device__ float g_l[B_DIM * 8 * H_DIM];   // l[b][k][h]
__device__ float g_f[B_DIM * H_DIM];
__device__ float g_o[B_DIM * H_DIM];
__device__ float g_h[B_DIM * H_DIM];
__device__ float g_c[B_DIM * H_DIM];
__device__ unsigned g_flags[NBLK];
__device__ unsigned g_epoch;

// ---------------------------------------------------------------------------
// f32x2 helpers (FFMA2 — only reachable via PTX fma.rn.f32x2)
// ---------------------------------------------------------------------------
__device__ __forceinline__ unsigned long long pack2(float v) {
    unsigned long long r;
    asm("mov.b64 %0, {%1, %1};" : "=l"(r) : "f"(v));
    return r;
}
__device__ __forceinline__ unsigned long long fma2(unsigned long long a,
                                                   unsigned long long b,
                                                   unsigned long long c) {
    unsigned long long d;
    asm("fma.rn.f32x2 %0, %1, %2, %3;" : "=l"(d) : "l"(a), "l"(b), "l"(c));
    return d;
}
__device__ __forceinline__ float2 unpack2(unsigned long long v) {
    float2 f;
    asm("mov.b64 {%0, %1}, %2;" : "=f"(f.x), "=f"(f.y) : "l"(v));
    return f;
}

__device__ __forceinline__ float fsig(float x) {
    x = fminf(fmaxf(x, -30.f), 30.f);
    return 1.f / (1.f + __expf(-x));
}
__device__ __forceinline__ float ftanh(float x) {
    x = fminf(fmaxf(x, -15.f), 15.f);
    float e = __expf(2.f * x);
    return (e - 1.f) / (e + 1.f);
}

struct Ptrs { const float* p[28]; };

// Per-matrix metadata: W (input proj), bias, input tensor X, channel count C.
__device__ __forceinline__ void matInfo(const Ptrs& P, int m,
                                        const float*& W, const float*& bias,
                                        const float*& X, int& C) {
    if (m < 4) {
        C = 8; X = P.p[0];
        W = P.p[8 + 3 * m]; bias = P.p[10 + 3 * m];
    } else if (m < 11) {
        int k = m - 4; C = 3;
        X = P.p[(k == 0) ? 1 : 2];                 // aux input gates: x1, then x2 (faithful quirk)
        W = P.p[20] + (size_t)k * 3 * H_DIM; bias = P.p[22] + (size_t)k * H_DIM;
    } else {
        int k = m - 11; C = 3;
        X = P.p[1 + k];                            // aux candidates: x1..x7
        W = P.p[23] + (size_t)k * 3 * H_DIM; bias = P.p[25] + (size_t)k * H_DIM;
    }
}

// ---------------------------------------------------------------------------
// Reset kernel: zero h0/c0 and barrier state (runs at every launch/replay)
// ---------------------------------------------------------------------------
__global__ void reset_kernel() {
    int i = blockIdx.x * blockDim.x + threadIdx.x;
    int n = gridDim.x * blockDim.x;
    if (i == 0) g_epoch = 0u;
    if (i < NBLK) g_flags[i] = 0u;
    for (int k = i; k < B_DIM * H_DIM; k += n) { g_h[k] = 0.f; g_c[k] = 0.f; }
}

// ---------------------------------------------------------------------------
// Transpose recurrent matrices:  Ut[m][g][h] = U_m[h][g] ; m==18 -> W_a
// ---------------------------------------------------------------------------
__global__ void transpose_kernel(Ptrs P) {
    int g = blockIdx.x, m = blockIdx.y;
    const float* U;
    if (m < 4)        U = P.p[9 + 3 * m];
    else if (m < 11)  U = P.p[21] + (size_t)(m - 4)  * H_DIM * H_DIM;
    else if (m < 18)  U = P.p[24] + (size_t)(m - 11) * H_DIM * H_DIM;
    else              U = P.p[26];
    for (int h = threadIdx.x; h < H_DIM; h += blockDim.x)
        g_Ut[((size_t)m * H_DIM + g) * H_DIM + h] = U[(size_t)h * H_DIM + g];
}

// ---------------------------------------------------------------------------
// Flag-array epoch grid barrier. Monotonic targets, no RMW contention.
// ---------------------------------------------------------------------------
__device__ __forceinline__ void grid_barrier(unsigned target) {
    __syncthreads();
    if (threadIdx.x == 0) {
        __threadfence();
        *(volatile unsigned*)&g_flags[blockIdx.x] = target;
    }
    if (blockIdx.x == 0) {
        for (int i = threadIdx.x; i < NBLK; i += THR)
            while (*(volatile unsigned*)&g_flags[i] < target) __nanosleep(32);
        __syncthreads();
        if (threadIdx.x == 0) {
            __threadfence();
            *(volatile unsigned*)&g_epoch = target;
        }
    }
    if (threadIdx.x == 0) {
        while (*(volatile unsigned*)&g_epoch < target) __nanosleep(32);
        __threadfence();
    }
    __syncthreads();
}

// ---------------------------------------------------------------------------
// Persistent recurrent kernel.
// Phase A CTA map: cta = p*16 + bg*4 + jb
//   p<9 gate-pair, bg<4 batch-group of 16, jb<4 j-tile of 128 (j = jb*128+tid)
//   pairs: p=0 -> (i, c) => l[0]; p=1 -> (f, o); p=2+k -> (4+k, 11+k) => l[1+k]
// Phase B CTA map (cta<128): b = cta>>1, ghalf = cta&1; thread handles 2 g's.
// ---------------------------------------------------------------------------
__global__ void __launch_bounds__(THR, 1)
main_kernel(Ptrs P, float* __restrict__ out) {
    __shared__ __align__(16) float sh[8192];                 // 32KB, reused A/B
    __shared__ float shxA[16 * 8];
    __shared__ float shxB[16 * 8];
    unsigned long long* shu = (unsigned long long*)sh;
    float2* sh2 = (float2*)sh;

    const int cta = blockIdx.x, tid = threadIdx.x;
    const int p  = cta >> 4;
    const int bg = (cta >> 2) & 3;
    const int jb = cta & 3;
    const int j  = jb * 128 + tid;
    int ma, mb;
    if      (p == 0) { ma = 0; mb = 2; }
    else if (p == 1) { ma = 1; mb = 3; }
    else             { ma = 4 + (p - 2); mb = 11 + (p - 2); }

    // Time-invariant per-thread params for the on-the-fly input projection.
    const float *WA, *WB, *bAp, *bBp, *XA, *XB;
    int Ca, Cb;
    matInfo(P, ma, WA, bAp, XA, Ca);
    matInfo(P, mb, WB, bBp, XB, Cb);
    float wA[8], wB[8];
    #pragma unroll
    for (int c = 0; c < 8; c++) { wA[c] = 0.f; wB[c] = 0.f; }
    for (int c = 0; c < Ca; c++) wA[c] = WA[(size_t)c * H_DIM + j];
    for (int c = 0; c < Cb; c++) wB[c] = WB[(size_t)c * H_DIM + j];
    const float bA = bAp[j], bB = bBp[j];

    const float* UtA = g_Ut + ((size_t)ma * H_DIM + j) * H_DIM;
    const float* UtB = g_Ut + ((size_t)mb * H_DIM + j) * H_DIM;
    const int bbase = bg * 16;
    const int bB_ = cta >> 1;      // phase-B batch
    const int gh  = cta & 1;       // phase-B g-half
    const float* b_a = P.p[27];

    union F4 { float4 v; float f[4]; };

    for (int t = 0; t < T_DIM; t++) {
        // ---------------- Phase A: z = x@W + b + h@U (fused gate pairs) ----
        // stage h for our 16 batches as float2 pairs: sh2[h*8 + bp]
        for (int i = tid; i < 4096; i += THR) {
            int hh = i >> 3, bp = i & 7;
            sh2[i] = make_float2(__ldcg(&g_h[(bbase + 2 * bp)     * H_DIM + hh]),
                                 __ldcg(&g_h[(bbase + 2 * bp + 1) * H_DIM + hh]));
        }
        // stage this step's raw inputs (<=256 scalars per CTA)
        for (int i = tid; i < 16 * Ca; i += THR) {
            int b = i / Ca, c = i - b * Ca;
            shxA[b * 8 + c] = XA[((size_t)(bbase + b) * Ca + c) * T_DIM + t];
        }
        for (int i = tid; i < 16 * Cb; i += THR) {
            int b = i / Cb, c = i - b * Cb;
            shxB[b * 8 + c] = XB[((size_t)(bbase + b) * Cb + c) * T_DIM + t];
        }
        __syncthreads();

        unsigned long long accA[8], accB[8];
        #pragma unroll
        for (int i = 0; i < 8; i++) { accA[i] = 0ull; accB[i] = 0ull; }

        const ulonglong2* shv = (const ulonglong2*)sh;
        const float4* UA4 = (const float4*)UtA;
        const float4* UB4 = (const float4*)UtB;
        #pragma unroll 2
        for (int hb = 0; hb < H_DIM / 4; hb++) {
            F4 ua, ub;
            ua.v = UA4[hb];
            ub.v = UB4[hb];
            #pragma unroll
            for (int q = 0; q < 4; q++) {
                int hh = hb * 4 + q;
                unsigned long long ua2 = pack2(ua.f[q]);
                unsigned long long ub2 = pack2(ub.f[q]);
                ulonglong2 h0 = shv[hh * 4 + 0];
                ulonglong2 h1 = shv[hh * 4 + 1];
                ulonglong2 h2 = shv[hh * 4 + 2];
                ulonglong2 h3 = shv[hh * 4 + 3];
                accA[0] = fma2(h0.x, ua2, accA[0]);  accA[1] = fma2(h0.y, ua2, accA[1]);
                accA[2] = fma2(h1.x, ua2, accA[2]);  accA[3] = fma2(h1.y, ua2, accA[3]);
                accA[4] = fma2(h2.x, ua2, accA[4]);  accA[5] = fma2(h2.y, ua2, accA[5]);
                accA[6] = fma2(h3.x, ua2, accA[6]);  accA[7] = fma2(h3.y, ua2, accA[7]);
                accB[0] = fma2(h0.x, ub2, accB[0]);  accB[1] = fma2(h0.y, ub2, accB[1]);
                accB[2] = fma2(h1.x, ub2, accB[2]);  accB[3] = fma2(h1.y, ub2, accB[3]);
                accB[4] = fma2(h2.x, ub2, accB[4]);  accB[5] = fma2(h2.y, ub2, accB[5]);
                accB[6] = fma2(h3.x, ub2, accB[6]);  accB[7] = fma2(h3.y, ub2, accB[7]);
            }
        }

        #pragma unroll
        for (int i = 0; i < 8; i++) {
            int b0 = 2 * i, b1 = 2 * i + 1;
            // on-the-fly input projections
            float pa0 = bA, pa1 = bA, pb0 = bB, pb1 = bB;
            for (int c = 0; c < Ca; c++) {
                pa0 = fmaf(shxA[b0 * 8 + c], wA[c], pa0);
                pa1 = fmaf(shxA[b1 * 8 + c], wA[c], pa1);
            }
            for (int c = 0; c < Cb; c++) {
                pb0 = fmaf(shxB[b0 * 8 + c], wB[c], pb0);
                pb1 = fmaf(shxB[b1 * 8 + c], wB[c], pb1);
            }
            float2 a2 = unpack2(accA[i]);
            float2 b2 = unpack2(accB[i]);
            float za0 = a2.x + pa0, za1 = a2.y + pa1;
            float zb0 = b2.x + pb0, zb1 = b2.y + pb1;
            int gb0 = bbase + b0, gb1 = bbase + b1;
            if (p == 1) {
                g_f[gb0 * H_DIM + j] = fsig(za0);
                g_f[gb1 * H_DIM + j] = fsig(za1);
                g_o[gb0 * H_DIM + j] = fsig(zb0);
                g_o[gb1 * H_DIM + j] = fsig(zb1);
            } else {
                int k = (p == 0) ? 0 : (p - 1);
                g_l[(gb0 * 8 + k) * H_DIM + j] = fsig(za0) * ftanh(zb0);
                g_l[(gb1 * 8 + k) * H_DIM + j] = fsig(za1) * ftanh(zb1);
            }
        }

        grid_barrier(2 * t + 1);

        // ---------------- Phase B: a = l @ W_a ; softmax combine ----------
        if (cta < 128) {
            // stage l[bB_][k][h] as k-pairs: sh2[h*4 + k2]
            for (int i = tid; i < 2048; i += THR) {
                int hh = i >> 2, k2 = i & 3;
                sh2[i] = make_float2(__ldcg(&g_l[(bB_ * 8 + 2 * k2)     * H_DIM + hh]),
                                     __ldcg(&g_l[(bB_ * 8 + 2 * k2 + 1) * H_DIM + hh]));
            }
            __syncthreads();

            const ulonglong2* sv = (const ulonglong2*)sh;
            for (int gi = 0; gi < 2; gi++) {
                int g = gh * 256 + gi * 128 + tid;
                const float4* W4 = (const float4*)(g_Ut + ((size_t)18 * H_DIM + g) * H_DIM);
                unsigned long long acc[4] = {0ull, 0ull, 0ull, 0ull};
                #pragma unroll 2
                for (int hb = 0; hb < H_DIM / 4; hb++) {
                    F4 w; w.v = W4[hb];
                    #pragma unroll
                    for (int q = 0; q < 4; q++) {
                        int hh = hb * 4 + q;
                        unsigned long long w2 = pack2(w.f[q]);
                        ulonglong2 l0 = sv[hh * 2 + 0];
                        ulonglong2 l1 = sv[hh * 2 + 1];
                        acc[0] = fma2(l0.x, w2, acc[0]);
                        acc[1] = fma2(l0.y, w2, acc[1]);
                        acc[2] = fma2(l1.x, w2, acc[2]);
                        acc[3] = fma2(l1.y, w2, acc[3]);
                    }
                }
                float a[8];
                { float2 q;
                  q = unpack2(acc[0]); a[0] = q.x; a[1] = q.y;
                  q = unpack2(acc[1]); a[2] = q.x; a[3] = q.y;
                  q = unpack2(acc[2]); a[4] = q.x; a[5] = q.y;
                  q = unpack2(acc[3]); a[6] = q.x; a[7] = q.y; }

                int idx = bB_ * H_DIM + g;
                float cold = g_c[idx];
                float ba = b_a[g];
                float u[8], mx = -1e30f;
                #pragma unroll
                for (int k = 0; k < 8; k++) {
                    u[k] = ftanh(fmaf(a[k], cold, ba));
                    mx = fmaxf(mx, u[k]);
                }
                float lg[8];
                { float2 q;
                  q = unpack2(shu[g * 4 + 0]); lg[0] = q.x; lg[1] = q.y;
                  q = unpack2(shu[g * 4 + 1]); lg[2] = q.x; lg[3] = q.y;
                  q = unpack2(shu[g * 4 + 2]); lg[4] = q.x; lg[5] = q.y;
                  q = unpack2(shu[g * 4 + 3]); lg[6] = q.x; lg[7] = q.y; }
                float es = 0.f, L = 0.f;
                #pragma unroll
                for (int k = 0; k < 8; k++) {
                    float e = __expf(u[k] - mx);
                    es += e;
                    L  += e * lg[k];
                }
                L /= es;
                float cnew = fmaf(__ldcg(&g_f[idx]), cold, L);
                g_c[idx] = cnew;
                float hn = __ldcg(&g_o[idx]) * ftanh(cnew);
                g_h[idx] = hn;
                out[(size_t)B_DIM * H_DIM + ((size_t)bB_ * T_DIM + t) * H_DIM + g] = hn;
                if (t == T_DIM - 1) out[(size_t)bB_ * H_DIM + g] = hn;
            }
        }

        grid_barrier(2 * t + 2);
    }
}

// ---------------------------------------------------------------------------
extern "C" void kernel_launch(void* const* d_in, const int* in_sizes, int n_in,
                              void* d_out, int out_size) {
    (void)in_sizes; (void)n_in; (void)out_size;
    Ptrs P;
    for (int i = 0; i < 28; i++) P.p[i] = (const float*)d_in[i];

    reset_kernel<<<64, 256>>>();
    transpose_kernel<<<dim3(H_DIM, 19), 128>>>(P);
    main_kernel<<<NBLK, THR>>>(P, (float*)d_out);
}